// round 1
// baseline (speedup 1.0000x reference)
#include <cuda_runtime.h>
#include <math.h>

#define BATCH   4096
#define VOCAB   100000

// ---------------- scratch (device globals; no allocation allowed) ----------------
__device__ float g_W0t[676 * 128];        // W0[o,i,j] -> [ij][o]
__device__ float g_W1t[3328 * 128];       // W1[o,i,j] -> [ij][o]
__device__ float g_emb[BATCH * 208];      // [b][j][k]  (26*8 = 208)
__device__ float g_lin[BATCH];
__device__ float g_X1[BATCH * 1024];      // [b][k][o]  (8*128)
__device__ float g_C[BATCH * 3328];       // [b][i*26+j]
__device__ float g_s1[BATCH];
__device__ float g_s2[BATCH];
__device__ float g_h1[BATCH * 256];
__device__ float g_h2[BATCH * 128];

// ---------------- prep: transpose CIN weights to K-major ----------------
__global__ void k_prep(const float* __restrict__ W0, const float* __restrict__ W1) {
    int t0 = blockIdx.x * blockDim.x + threadIdx.x;
    int stride = gridDim.x * blockDim.x;
    for (int u = t0; u < 676 * 128; u += stride) {
        int ij = u >> 7, o = u & 127;
        g_W0t[u] = W0[o * 676 + ij];
    }
    for (int u = t0; u < 3328 * 128; u += stride) {
        int ij = u >> 7, o = u & 127;
        g_W1t[u] = W1[o * 3328 + ij];
    }
}

// ---------------- gather embeddings + linear term (1 warp / sample) ----------------
__global__ void k_gather(const float* __restrict__ inputs,
                         const float* __restrict__ emb_tables,
                         const float* __restrict__ linW,
                         const float* __restrict__ linb) {
    int warp = (blockIdx.x * blockDim.x + threadIdx.x) >> 5;
    int lane = threadIdx.x & 31;
    if (warp >= BATCH) return;
    int b = warp;
    const float* row = inputs + b * 39;
    if (lane < 26) {
        int idx = (int)row[13 + lane];
        const float4* src = (const float4*)(emb_tables + ((size_t)lane * VOCAB + idx) * 8);
        float4* dst = (float4*)(g_emb + b * 208 + lane * 8);
        dst[0] = src[0];
        dst[1] = src[1];
    }
    float s = 0.f;
    for (int t = lane; t < 39; t += 32) s += row[t] * linW[t];
    #pragma unroll
    for (int o = 16; o; o >>= 1) s += __shfl_down_sync(0xffffffffu, s, o);
    if (lane == 0) g_lin[b] = s + linb[0];
}

// ---------------- CIN layer 0 GEMM: rows = (b,k) 32768, cols = o 128, K = 676 -----
// A[(b,k),(i,j)] = e[b,i,k]*e[b,j,k] built in smem from a 16-sample emb tile.
__global__ __launch_bounds__(256) void k_cin0(const float* __restrict__ bias0) {
    __shared__ float Es[16 * 208];
    __shared__ float As[26 * 128];   // [j][r]
    __shared__ float Bs[26 * 128];   // [j][o]
    int tid = threadIdx.x;
    int b0 = blockIdx.x * 16;

    for (int t = tid; t < 16 * 208; t += 256) Es[t] = g_emb[b0 * 208 + t];

    float acc[8][8];
    #pragma unroll
    for (int rr = 0; rr < 8; rr++)
        #pragma unroll
        for (int cc = 0; cc < 8; cc++) acc[rr][cc] = 0.f;

    int r0 = (tid >> 4) << 3;
    int c0 = (tid & 15) << 3;
    __syncthreads();

    for (int i = 0; i < 26; i++) {
        for (int t = tid; t < 26 * 128; t += 256) Bs[t] = g_W0t[i * 26 * 128 + t];
        for (int t = tid; t < 26 * 128; t += 256) {
            int j = t >> 7, r = t & 127;
            int bl = r >> 3, k = r & 7;
            As[t] = Es[bl * 208 + i * 8 + k] * Es[bl * 208 + j * 8 + k];
        }
        __syncthreads();
        #pragma unroll 2
        for (int j = 0; j < 26; j++) {
            float4 a0 = *(const float4*)&As[j * 128 + r0];
            float4 a1 = *(const float4*)&As[j * 128 + r0 + 4];
            float4 w0 = *(const float4*)&Bs[j * 128 + c0];
            float4 w1 = *(const float4*)&Bs[j * 128 + c0 + 4];
            float a[8] = {a0.x, a0.y, a0.z, a0.w, a1.x, a1.y, a1.z, a1.w};
            float w[8] = {w0.x, w0.y, w0.z, w0.w, w1.x, w1.y, w1.z, w1.w};
            #pragma unroll
            for (int rr = 0; rr < 8; rr++)
                #pragma unroll
                for (int cc = 0; cc < 8; cc++) acc[rr][cc] += a[rr] * w[cc];
        }
        __syncthreads();
    }

    float bias[8];
    #pragma unroll
    for (int cc = 0; cc < 8; cc++) bias[cc] = bias0[c0 + cc];
    #pragma unroll
    for (int rr = 0; rr < 8; rr++) {
        int r = r0 + rr;
        int b = b0 + (r >> 3);
        int k = r & 7;
        float4 v0 = {acc[rr][0] + bias[0], acc[rr][1] + bias[1],
                     acc[rr][2] + bias[2], acc[rr][3] + bias[3]};
        float4 v1 = {acc[rr][4] + bias[4], acc[rr][5] + bias[5],
                     acc[rr][6] + bias[6], acc[rr][7] + bias[7]};
        *(float4*)&g_X1[b * 1024 + k * 128 + c0] = v0;
        *(float4*)&g_X1[b * 1024 + k * 128 + c0 + 4] = v1;
    }
}

// ---------------- C[b,i,j] = sum_k X1[b,k,i]*emb[b,j,k]; also s1 ----------------
__global__ __launch_bounds__(128) void k_C(const float* __restrict__ clinW) {
    __shared__ float Xs[1024];
    __shared__ float Es[208];
    __shared__ float red[128];
    int b = blockIdx.x, tid = threadIdx.x;
    for (int t = tid; t < 1024; t += 128) Xs[t] = g_X1[b * 1024 + t];
    for (int t = tid; t < 208; t += 128) Es[t] = g_emb[b * 208 + t];
    __syncthreads();
    int i = tid;
    float x[8];
    #pragma unroll
    for (int k = 0; k < 8; k++) x[k] = Xs[k * 128 + i];
    float* Crow = g_C + (size_t)b * 3328 + i * 26;
    #pragma unroll 2
    for (int j = 0; j < 26; j++) {
        float a = 0.f;
        #pragma unroll
        for (int k = 0; k < 8; k++) a += x[k] * Es[j * 8 + k];
        Crow[j] = a;
    }
    float ssum = 0.f;
    #pragma unroll
    for (int k = 0; k < 8; k++) ssum += x[k];
    red[tid] = ssum * clinW[i];
    __syncthreads();
    for (int off = 64; off; off >>= 1) {
        if (tid < off) red[tid] += red[tid + off];
        __syncthreads();
    }
    if (tid == 0) g_s1[b] = red[0];
}

// ---------------- CIN layer 1 GEMM (k-sum folded): (4096 x 3328)@(3328 x 128) ----
// 32 b-rows x all 128 o-cols per block; epilogue reduces with cin_lin_W[128:] -> s2.
__global__ __launch_bounds__(256) void k_cin1(const float* __restrict__ bias1,
                                              const float* __restrict__ clinW) {
    __shared__ float As[32 * 33];    // [r][kk], pad 33
    __shared__ float Bs[32 * 128];   // [kk][o]
    __shared__ float red[32 * 32];
    int tid = threadIdx.x;
    int b0 = blockIdx.x * 32;
    int r0 = (tid >> 5) << 2;
    int c0 = (tid & 31) << 2;
    float acc[4][4];
    #pragma unroll
    for (int rr = 0; rr < 4; rr++)
        #pragma unroll
        for (int cc = 0; cc < 4; cc++) acc[rr][cc] = 0.f;

    for (int k0 = 0; k0 < 3328; k0 += 32) {
        {
            int r = tid >> 5, kk = tid & 31;
            #pragma unroll
            for (int rr = 0; rr < 32; rr += 8)
                As[(r + rr) * 33 + kk] = g_C[(size_t)(b0 + r + rr) * 3328 + k0 + kk];
        }
        for (int t = tid; t < 32 * 128; t += 256) Bs[t] = g_W1t[(size_t)k0 * 128 + t];
        __syncthreads();
        #pragma unroll 4
        for (int kk = 0; kk < 32; kk++) {
            float a[4];
            #pragma unroll
            for (int rr = 0; rr < 4; rr++) a[rr] = As[(r0 + rr) * 33 + kk];
            float4 bv = *(const float4*)&Bs[kk * 128 + c0];
            float w[4] = {bv.x, bv.y, bv.z, bv.w};
            #pragma unroll
            for (int rr = 0; rr < 4; rr++)
                #pragma unroll
                for (int cc = 0; cc < 4; cc++) acc[rr][cc] += a[rr] * w[cc];
        }
        __syncthreads();
    }

    // epilogue: s2[b] = sum_o (acc + 8*b1[o]) * clinW[128+o]
    #pragma unroll
    for (int rr = 0; rr < 4; rr++) {
        float p = 0.f;
        #pragma unroll
        for (int cc = 0; cc < 4; cc++) {
            int o = c0 + cc;
            p += (acc[rr][cc] + 8.f * bias1[o]) * clinW[128 + o];
        }
        red[(r0 + rr) * 32 + (tid & 31)] = p;
    }
    __syncthreads();
    if (tid < 32) {
        float s = 0.f;
        #pragma unroll 8
        for (int t = 0; t < 32; t++) s += red[tid * 32 + t];
        g_s2[b0 + tid] = s;
    }
}

// ---------------- MLP layer 1: (4096 x 221)@(221 x 256), relu ----------------
__global__ __launch_bounds__(256) void k_mlp1(const float* __restrict__ inputs,
                                              const float* __restrict__ W1,
                                              const float* __restrict__ b1) {
    __shared__ float As[64 * 33];
    __shared__ float Bs[32 * 64];
    int tid = threadIdx.x;
    int b0 = blockIdx.x * 64;
    int n0 = blockIdx.y * 64;
    int r0 = (tid >> 4) << 2;
    int c0 = (tid & 15) << 2;
    float acc[4][4];
    #pragma unroll
    for (int rr = 0; rr < 4; rr++)
        #pragma unroll
        for (int cc = 0; cc < 4; cc++) acc[rr][cc] = 0.f;

    for (int k0 = 0; k0 < 224; k0 += 32) {
        {
            int r = tid >> 5, kk = tid & 31;
            int k = k0 + kk;
            #pragma unroll
            for (int rr = 0; rr < 64; rr += 8) {
                int b = b0 + r + rr;
                float v = 0.f;
                if (k < 13) v = inputs[b * 39 + k];
                else if (k < 221) v = g_emb[b * 208 + k - 13];
                As[(r + rr) * 33 + kk] = v;
            }
        }
        for (int t = tid; t < 32 * 64; t += 256) {
            int kk = t >> 6, c = t & 63;
            int k = k0 + kk;
            Bs[t] = (k < 221) ? W1[k * 256 + n0 + c] : 0.f;
        }
        __syncthreads();
        #pragma unroll 4
        for (int kk = 0; kk < 32; kk++) {
            float a[4];
            #pragma unroll
            for (int rr = 0; rr < 4; rr++) a[rr] = As[(r0 + rr) * 33 + kk];
            float4 bv = *(const float4*)&Bs[kk * 64 + c0];
            float w[4] = {bv.x, bv.y, bv.z, bv.w};
            #pragma unroll
            for (int rr = 0; rr < 4; rr++)
                #pragma unroll
                for (int cc = 0; cc < 4; cc++) acc[rr][cc] += a[rr] * w[cc];
        }
        __syncthreads();
    }

    #pragma unroll
    for (int rr = 0; rr < 4; rr++) {
        int b = b0 + r0 + rr;
        float4 v;
        v.x = fmaxf(acc[rr][0] + b1[n0 + c0 + 0], 0.f);
        v.y = fmaxf(acc[rr][1] + b1[n0 + c0 + 1], 0.f);
        v.z = fmaxf(acc[rr][2] + b1[n0 + c0 + 2], 0.f);
        v.w = fmaxf(acc[rr][3] + b1[n0 + c0 + 3], 0.f);
        *(float4*)&g_h1[b * 256 + n0 + c0] = v;
    }
}

// ---------------- MLP layer 2: (4096 x 256)@(256 x 128), relu ----------------
__global__ __launch_bounds__(256) void k_mlp2(const float* __restrict__ W2,
                                              const float* __restrict__ b2) {
    __shared__ float As[64 * 33];
    __shared__ float Bs[32 * 64];
    int tid = threadIdx.x;
    int b0 = blockIdx.x * 64;
    int n0 = blockIdx.y * 64;
    int r0 = (tid >> 4) << 2;
    int c0 = (tid & 15) << 2;
    float acc[4][4];
    #pragma unroll
    for (int rr = 0; rr < 4; rr++)
        #pragma unroll
        for (int cc = 0; cc < 4; cc++) acc[rr][cc] = 0.f;

    for (int k0 = 0; k0 < 256; k0 += 32) {
        {
            int r = tid >> 5, kk = tid & 31;
            #pragma unroll
            for (int rr = 0; rr < 64; rr += 8)
                As[(r + rr) * 33 + kk] = g_h1[(b0 + r + rr) * 256 + k0 + kk];
        }
        for (int t = tid; t < 32 * 64; t += 256) {
            int kk = t >> 6, c = t & 63;
            Bs[t] = W2[(k0 + kk) * 128 + n0 + c];
        }
        __syncthreads();
        #pragma unroll 4
        for (int kk = 0; kk < 32; kk++) {
            float a[4];
            #pragma unroll
            for (int rr = 0; rr < 4; rr++) a[rr] = As[(r0 + rr) * 33 + kk];
            float4 bv = *(const float4*)&Bs[kk * 64 + c0];
            float w[4] = {bv.x, bv.y, bv.z, bv.w};
            #pragma unroll
            for (int rr = 0; rr < 4; rr++)
                #pragma unroll
                for (int cc = 0; cc < 4; cc++) acc[rr][cc] += a[rr] * w[cc];
        }
        __syncthreads();
    }

    #pragma unroll
    for (int rr = 0; rr < 4; rr++) {
        int b = b0 + r0 + rr;
        float4 v;
        v.x = fmaxf(acc[rr][0] + b2[n0 + c0 + 0], 0.f);
        v.y = fmaxf(acc[rr][1] + b2[n0 + c0 + 1], 0.f);
        v.z = fmaxf(acc[rr][2] + b2[n0 + c0 + 2], 0.f);
        v.w = fmaxf(acc[rr][3] + b2[n0 + c0 + 3], 0.f);
        *(float4*)&g_h2[b * 128 + n0 + c0] = v;
    }
}

// ---------------- MLP L3 + L4 + combine + sigmoid ----------------
__global__ __launch_bounds__(128) void k_final(const float* __restrict__ W3,
                                               const float* __restrict__ b3,
                                               const float* __restrict__ W4,
                                               const float* __restrict__ b4,
                                               const float* __restrict__ clinb,
                                               float* __restrict__ out) {
    __shared__ float W3s[128 * 64];
    __shared__ float hs[16 * 128];
    __shared__ float W4s[64];
    __shared__ float red[4];
    int tid = threadIdx.x;
    int b0 = blockIdx.x * 16;
    for (int t = tid; t < 128 * 64; t += 128) W3s[t] = W3[t];
    for (int t = tid; t < 16 * 128; t += 128) hs[t] = g_h2[b0 * 128 + t];
    if (tid < 64) W4s[tid] = W4[tid];
    __syncthreads();

    int sh = tid >> 6;   // sample-half 0/1
    int o = tid & 63;
    float w4 = W4s[o];
    float b3o = b3[o];
    for (int ss = 0; ss < 8; ss++) {
        int s = ss * 2 + sh;
        float acc = 0.f;
        #pragma unroll 8
        for (int k = 0; k < 128; k++) acc += hs[s * 128 + k] * W3s[k * 64 + o];
        float h3 = fmaxf(acc + b3o, 0.f);
        float p = h3 * w4;
        #pragma unroll
        for (int off = 16; off; off >>= 1) p += __shfl_down_sync(0xffffffffu, p, off);
        if ((tid & 31) == 0) red[tid >> 5] = p;
        __syncthreads();
        if (o == 0) {
            float d = fmaxf(red[sh * 2] + red[sh * 2 + 1] + b4[0], 0.f);
            int b = b0 + s;
            float cin = fmaxf(g_s1[b] + g_s2[b] + clinb[0], 0.f);
            float logit = g_lin[b] + cin + d;
            out[b] = 1.f / (1.f + expf(-logit));
        }
        __syncthreads();
    }
}

// ---------------- launch ----------------
extern "C" void kernel_launch(void* const* d_in, const int* in_sizes, int n_in,
                              void* d_out, int out_size) {
    const float* inputs     = (const float*)d_in[0];
    const float* emb_tables = (const float*)d_in[1];
    const float* linear_W   = (const float*)d_in[2];
    const float* linear_b   = (const float*)d_in[3];
    const float* W_cin0     = (const float*)d_in[4];
    const float* b_cin0     = (const float*)d_in[5];
    const float* W_cin1     = (const float*)d_in[6];
    const float* b_cin1     = (const float*)d_in[7];
    const float* cin_lin_W  = (const float*)d_in[8];
    const float* cin_lin_b  = (const float*)d_in[9];
    const float* d_W1       = (const float*)d_in[10];
    const float* d_b1       = (const float*)d_in[11];
    const float* d_W2       = (const float*)d_in[12];
    const float* d_b2       = (const float*)d_in[13];
    const float* d_W3       = (const float*)d_in[14];
    const float* d_b3       = (const float*)d_in[15];
    const float* d_W4       = (const float*)d_in[16];
    const float* d_b4       = (const float*)d_in[17];
    float* out = (float*)d_out;

    k_prep<<<512, 256>>>(W_cin0, W_cin1);
    k_gather<<<512, 256>>>(inputs, emb_tables, linear_W, linear_b);
    k_cin0<<<256, 256>>>(b_cin0);
    k_C<<<BATCH, 128>>>(cin_lin_W);
    k_cin1<<<128, 256>>>(b_cin1, cin_lin_W);
    k_mlp1<<<dim3(64, 4), 256>>>(inputs, d_W1, d_b1);
    k_mlp2<<<dim3(64, 2), 256>>>(d_W2, d_b2);
    k_final<<<256, 128>>>(d_W3, d_b3, d_W4, d_b4, cin_lin_b, out);
}

// round 2
// speedup vs baseline: 3.2786x; 3.2786x over previous
#include <cuda_runtime.h>
#include <math.h>

#define BATCH   4096
#define VOCAB   100000
#define NPAIR   351
#define NPAIRP  352   // padded to 32

// ---------------- scratch (device globals; no allocation allowed) ----------------
__device__ float g_W0s[NPAIRP * 128];     // symmetric-folded W0: [pair][o]
__device__ int   g_pairs[NPAIRP];         // (i<<8)|j per pair
__device__ float g_V[3328];               // V[i*26+j] = sum_o clinW[128+o]*W1[o,i,j]
__device__ float g_cbias;                 // 8 * sum_o clinW[128+o]*b1[o]
__device__ float g_emb[BATCH * 208];      // [b][j][k]  (26*8 = 208)
__device__ float g_lin[BATCH];
__device__ float g_s1[BATCH];
__device__ float g_s2[BATCH];
__device__ float g_h1[BATCH * 256];
__device__ float g_h2[BATCH * 128];

// ---------------- prep: fold weights ----------------
__global__ void k_prep(const float* __restrict__ W0, const float* __restrict__ W1,
                       const float* __restrict__ clinW, const float* __restrict__ b1) {
    int t0 = blockIdx.x * blockDim.x + threadIdx.x;
    int stride = gridDim.x * blockDim.x;
    for (int p = t0; p < NPAIRP; p += stride) {
        if (p < NPAIR) {
            int i = 0, rem = p;
            while (rem >= 26 - i) { rem -= 26 - i; i++; }
            g_pairs[p] = (i << 8) | (i + rem);
        } else g_pairs[p] = 0;
    }
    for (int u = t0; u < NPAIRP * 128; u += stride) {
        int p = u >> 7, o = u & 127;
        float v = 0.f;
        if (p < NPAIR) {
            int i = 0, rem = p;
            while (rem >= 26 - i) { rem -= 26 - i; i++; }
            int j = i + rem;
            v = W0[o * 676 + i * 26 + j];
            if (j > i) v += W0[o * 676 + j * 26 + i];
        }
        g_W0s[u] = v;
    }
    for (int u = t0; u < 3328; u += stride) {
        float s = 0.f;
        #pragma unroll 8
        for (int o = 0; o < 128; o++) s += clinW[128 + o] * W1[o * 3328 + u];
        g_V[u] = s;
    }
    if (t0 == 0) {
        float s = 0.f;
        for (int o = 0; o < 128; o++) s += clinW[128 + o] * b1[o];
        g_cbias = 8.f * s;
    }
}

// ---------------- gather embeddings + linear term (1 warp / sample) ----------------
__global__ void k_gather(const float* __restrict__ inputs,
                         const float* __restrict__ emb_tables,
                         const float* __restrict__ linW,
                         const float* __restrict__ linb) {
    int warp = (blockIdx.x * blockDim.x + threadIdx.x) >> 5;
    int lane = threadIdx.x & 31;
    if (warp >= BATCH) return;
    int b = warp;
    const float* row = inputs + b * 39;
    if (lane < 26) {
        int idx = (int)row[13 + lane];
        const float4* src = (const float4*)(emb_tables + ((size_t)lane * VOCAB + idx) * 8);
        float4* dst = (float4*)(g_emb + b * 208 + lane * 8);
        dst[0] = src[0];
        dst[1] = src[1];
    }
    float s = 0.f;
    for (int t = lane; t < 39; t += 32) s += row[t] * linW[t];
    #pragma unroll
    for (int o = 16; o; o >>= 1) s += __shfl_down_sync(0xffffffffu, s, o);
    if (lane == 0) g_lin[b] = s + linb[0];
}

// ---------------- fully-fused CIN: GEMM (32768 x 128, K=351 sym pairs) ----------
// + epilogue computing s1 (cin first 128 feats) and s2 (folded layer-1) per sample.
// 16 samples per block; X1 never leaves registers.
__global__ __launch_bounds__(256) void k_cin0f(const float* __restrict__ bias0,
                                               const float* __restrict__ clinW) {
    __shared__ float Es[16 * 208];     // emb tile [bl][j][k]
    __shared__ float As[32 * 128];     // [pp][r]  r=(bl,k)
    __shared__ float Bs[32 * 128];     // [pp][o]
    __shared__ int   Ps[NPAIRP];
    int tid = threadIdx.x;
    int b0 = blockIdx.x * 16;

    for (int t = tid; t < 16 * 208; t += 256) Es[t] = g_emb[b0 * 208 + t];
    for (int t = tid; t < NPAIRP; t += 256) Ps[t] = g_pairs[t];

    float acc[8][8];
    #pragma unroll
    for (int rr = 0; rr < 8; rr++)
        #pragma unroll
        for (int cc = 0; cc < 8; cc++) acc[rr][cc] = 0.f;

    int bl = tid >> 4;            // sample within tile (each thread: 1 sample, all 8 k)
    int r0 = bl << 3;
    int c0 = (tid & 15) << 3;     // 8 output channels
    __syncthreads();

    for (int c = 0; c < NPAIRP / 32; c++) {
        for (int t = tid; t < 32 * 128; t += 256) Bs[t] = g_W0s[c * 32 * 128 + t];
        for (int t = tid; t < 32 * 128; t += 256) {
            int pp = t >> 7, r = t & 127;
            int pr = Ps[c * 32 + pp];
            int i = pr >> 8, j = pr & 255;
            int sb = (r >> 3) * 208, k = r & 7;
            As[t] = Es[sb + i * 8 + k] * Es[sb + j * 8 + k];
        }
        __syncthreads();
        #pragma unroll 4
        for (int kk = 0; kk < 32; kk++) {
            float4 a0 = *(const float4*)&As[kk * 128 + r0];
            float4 a1 = *(const float4*)&As[kk * 128 + r0 + 4];
            float4 w0 = *(const float4*)&Bs[kk * 128 + c0];
            float4 w1 = *(const float4*)&Bs[kk * 128 + c0 + 4];
            float a[8] = {a0.x, a0.y, a0.z, a0.w, a1.x, a1.y, a1.z, a1.w};
            float w[8] = {w0.x, w0.y, w0.z, w0.w, w1.x, w1.y, w1.z, w1.w};
            #pragma unroll
            for (int rr = 0; rr < 8; rr++)
                #pragma unroll
                for (int cc = 0; cc < 8; cc++) acc[rr][cc] += a[rr] * w[cc];
        }
        __syncthreads();
    }

    // epilogue: X1[b, k=rr, i=c0+cc] = acc + b0[i];
    // s1 += clinW[i]*X1 ; s2 += X1 * u[b,i,k],  u = sum_j V[i,j]*e[b,j,k]
    float s1p = 0.f, s2p = 0.f;
    #pragma unroll
    for (int cc = 0; cc < 8; cc++) {
        int i = c0 + cc;
        float bv = bias0[i];
        float cw = clinW[i];
        const float* Vrow = g_V + i * 26;
        float u[8];
        #pragma unroll
        for (int rr = 0; rr < 8; rr++) u[rr] = 0.f;
        #pragma unroll 2
        for (int j = 0; j < 26; j++) {
            float vj = Vrow[j];
            #pragma unroll
            for (int rr = 0; rr < 8; rr++) u[rr] += vj * Es[bl * 208 + j * 8 + rr];
        }
        #pragma unroll
        for (int rr = 0; rr < 8; rr++) {
            float x = acc[rr][cc] + bv;
            s1p += cw * x;
            s2p += x * u[rr];
        }
    }
    #pragma unroll
    for (int off = 8; off; off >>= 1) {
        s1p += __shfl_down_sync(0xffffffffu, s1p, off, 16);
        s2p += __shfl_down_sync(0xffffffffu, s2p, off, 16);
    }
    if ((tid & 15) == 0) {
        g_s1[b0 + bl] = s1p;
        g_s2[b0 + bl] = s2p;
    }
}

// ---------------- MLP layer 1: (4096 x 221)@(221 x 256), relu ----------------
__global__ __launch_bounds__(256) void k_mlp1(const float* __restrict__ inputs,
                                              const float* __restrict__ W1,
                                              const float* __restrict__ b1) {
    __shared__ float As[64 * 33];
    __shared__ float Bs[32 * 64];
    int tid = threadIdx.x;
    int b0 = blockIdx.x * 64;
    int n0 = blockIdx.y * 64;
    int r0 = (tid >> 4) << 2;
    int c0 = (tid & 15) << 2;
    float acc[4][4];
    #pragma unroll
    for (int rr = 0; rr < 4; rr++)
        #pragma unroll
        for (int cc = 0; cc < 4; cc++) acc[rr][cc] = 0.f;

    for (int k0 = 0; k0 < 224; k0 += 32) {
        {
            int r = tid >> 5, kk = tid & 31;
            int k = k0 + kk;
            #pragma unroll
            for (int rr = 0; rr < 64; rr += 8) {
                int b = b0 + r + rr;
                float v = 0.f;
                if (k < 13) v = inputs[b * 39 + k];
                else if (k < 221) v = g_emb[b * 208 + k - 13];
                As[(r + rr) * 33 + kk] = v;
            }
        }
        for (int t = tid; t < 32 * 64; t += 256) {
            int kk = t >> 6, c = t & 63;
            int k = k0 + kk;
            Bs[t] = (k < 221) ? W1[k * 256 + n0 + c] : 0.f;
        }
        __syncthreads();
        #pragma unroll 4
        for (int kk = 0; kk < 32; kk++) {
            float a[4];
            #pragma unroll
            for (int rr = 0; rr < 4; rr++) a[rr] = As[(r0 + rr) * 33 + kk];
            float4 bv = *(const float4*)&Bs[kk * 64 + c0];
            float w[4] = {bv.x, bv.y, bv.z, bv.w};
            #pragma unroll
            for (int rr = 0; rr < 4; rr++)
                #pragma unroll
                for (int cc = 0; cc < 4; cc++) acc[rr][cc] += a[rr] * w[cc];
        }
        __syncthreads();
    }

    #pragma unroll
    for (int rr = 0; rr < 4; rr++) {
        int b = b0 + r0 + rr;
        float4 v;
        v.x = fmaxf(acc[rr][0] + b1[n0 + c0 + 0], 0.f);
        v.y = fmaxf(acc[rr][1] + b1[n0 + c0 + 1], 0.f);
        v.z = fmaxf(acc[rr][2] + b1[n0 + c0 + 2], 0.f);
        v.w = fmaxf(acc[rr][3] + b1[n0 + c0 + 3], 0.f);
        *(float4*)&g_h1[b * 256 + n0 + c0] = v;
    }
}

// ---------------- MLP layer 2: (4096 x 256)@(256 x 128), relu ----------------
__global__ __launch_bounds__(256) void k_mlp2(const float* __restrict__ W2,
                                              const float* __restrict__ b2) {
    __shared__ float As[64 * 33];
    __shared__ float Bs[32 * 64];
    int tid = threadIdx.x;
    int b0 = blockIdx.x * 64;
    int n0 = blockIdx.y * 64;
    int r0 = (tid >> 4) << 2;
    int c0 = (tid & 15) << 2;
    float acc[4][4];
    #pragma unroll
    for (int rr = 0; rr < 4; rr++)
        #pragma unroll
        for (int cc = 0; cc < 4; cc++) acc[rr][cc] = 0.f;

    for (int k0 = 0; k0 < 256; k0 += 32) {
        {
            int r = tid >> 5, kk = tid & 31;
            #pragma unroll
            for (int rr = 0; rr < 64; rr += 8)
                As[(r + rr) * 33 + kk] = g_h1[(b0 + r + rr) * 256 + k0 + kk];
        }
        for (int t = tid; t < 32 * 64; t += 256) {
            int kk = t >> 6, c = t & 63;
            Bs[t] = W2[(k0 + kk) * 128 + n0 + c];
        }
        __syncthreads();
        #pragma unroll 4
        for (int kk = 0; kk < 32; kk++) {
            float a[4];
            #pragma unroll
            for (int rr = 0; rr < 4; rr++) a[rr] = As[(r0 + rr) * 33 + kk];
            float4 bv = *(const float4*)&Bs[kk * 64 + c0];
            float w[4] = {bv.x, bv.y, bv.z, bv.w};
            #pragma unroll
            for (int rr = 0; rr < 4; rr++)
                #pragma unroll
                for (int cc = 0; cc < 4; cc++) acc[rr][cc] += a[rr] * w[cc];
        }
        __syncthreads();
    }

    #pragma unroll
    for (int rr = 0; rr < 4; rr++) {
        int b = b0 + r0 + rr;
        float4 v;
        v.x = fmaxf(acc[rr][0] + b2[n0 + c0 + 0], 0.f);
        v.y = fmaxf(acc[rr][1] + b2[n0 + c0 + 1], 0.f);
        v.z = fmaxf(acc[rr][2] + b2[n0 + c0 + 2], 0.f);
        v.w = fmaxf(acc[rr][3] + b2[n0 + c0 + 3], 0.f);
        *(float4*)&g_h2[b * 128 + n0 + c0] = v;
    }
}

// ---------------- MLP L3 + L4 + combine + sigmoid ----------------
__global__ __launch_bounds__(128) void k_final(const float* __restrict__ W3,
                                               const float* __restrict__ b3,
                                               const float* __restrict__ W4,
                                               const float* __restrict__ b4,
                                               const float* __restrict__ clinb,
                                               float* __restrict__ out) {
    __shared__ float W3s[128 * 64];
    __shared__ float hs[16 * 128];
    __shared__ float W4s[64];
    __shared__ float red[4];
    int tid = threadIdx.x;
    int b0 = blockIdx.x * 16;
    for (int t = tid; t < 128 * 64; t += 128) W3s[t] = W3[t];
    for (int t = tid; t < 16 * 128; t += 128) hs[t] = g_h2[b0 * 128 + t];
    if (tid < 64) W4s[tid] = W4[tid];
    __syncthreads();

    int sh = tid >> 6;
    int o = tid & 63;
    float w4 = W4s[o];
    float b3o = b3[o];
    for (int ss = 0; ss < 8; ss++) {
        int s = ss * 2 + sh;
        float acc = 0.f;
        #pragma unroll 8
        for (int k = 0; k < 128; k++) acc += hs[s * 128 + k] * W3s[k * 64 + o];
        float h3 = fmaxf(acc + b3o, 0.f);
        float p = h3 * w4;
        #pragma unroll
        for (int off = 16; off; off >>= 1) p += __shfl_down_sync(0xffffffffu, p, off);
        if ((tid & 31) == 0) red[tid >> 5] = p;
        __syncthreads();
        if (o == 0) {
            float d = fmaxf(red[sh * 2] + red[sh * 2 + 1] + b4[0], 0.f);
            int b = b0 + s;
            float cin = fmaxf(g_s1[b] + g_s2[b] + g_cbias + clinb[0], 0.f);
            float logit = g_lin[b] + cin + d;
            out[b] = 1.f / (1.f + expf(-logit));
        }
        __syncthreads();
    }
}

// ---------------- launch ----------------
extern "C" void kernel_launch(void* const* d_in, const int* in_sizes, int n_in,
                              void* d_out, int out_size) {
    const float* inputs     = (const float*)d_in[0];
    const float* emb_tables = (const float*)d_in[1];
    const float* linear_W   = (const float*)d_in[2];
    const float* linear_b   = (const float*)d_in[3];
    const float* W_cin0     = (const float*)d_in[4];
    const float* b_cin0     = (const float*)d_in[5];
    const float* W_cin1     = (const float*)d_in[6];
    const float* b_cin1     = (const float*)d_in[7];
    const float* cin_lin_W  = (const float*)d_in[8];
    const float* cin_lin_b  = (const float*)d_in[9];
    const float* d_W1       = (const float*)d_in[10];
    const float* d_b1       = (const float*)d_in[11];
    const float* d_W2       = (const float*)d_in[12];
    const float* d_b2       = (const float*)d_in[13];
    const float* d_W3       = (const float*)d_in[14];
    const float* d_b3       = (const float*)d_in[15];
    const float* d_W4       = (const float*)d_in[16];
    const float* d_b4       = (const float*)d_in[17];
    float* out = (float*)d_out;

    k_prep<<<256, 256>>>(W_cin0, W_cin1, cin_lin_W, b_cin1);
    k_gather<<<512, 256>>>(inputs, emb_tables, linear_W, linear_b);
    k_cin0f<<<256, 256>>>(b_cin0, cin_lin_W);
    k_mlp1<<<dim3(64, 4), 256>>>(inputs, d_W1, d_b1);
    k_mlp2<<<dim3(64, 2), 256>>>(d_W2, d_b2);
    k_final<<<256, 128>>>(d_W3, d_b3, d_W4, d_b4, cin_lin_b, out);
}